// round 10
// baseline (speedup 1.0000x reference)
#include <cuda_runtime.h>
#include <cuda_bf16.h>
#include <math.h>
#include <stdint.h>

// ---------------- problem constants ----------------
#define BB 2
#define SS 1024
#define NN (BB*SS)          // 2048 tokens
#define EE 768
#define HH 12
#define DD 64
#define II 3072
#define LL 4
#define RH 128
#define MAXD 4
#define VV 50257
#define QKVW (3*EE)         // 2304

// ---------------- scratch (device globals; no allocation allowed) ----------------
__device__ float g_h   [NN*EE];
__device__ float g_hn  [NN*EE];
__device__ float g_qkv [NN*QKVW];
__device__ float g_attn[NN*EE];
__device__ float g_ffa [NN*II];
__device__ float g_rlog[NN*MAXD];
__device__ int   g_dep [NN];
__device__ float g_loss[1];

// ---------------- embedding ----------------
__global__ void embed_kernel(const int* __restrict__ ids,
                             const float* __restrict__ tok,
                             const float* __restrict__ pos,
                             float* __restrict__ h) {
    int i = blockIdx.x * blockDim.x + threadIdx.x;
    if (i >= NN*EE) return;
    int n = i / EE, e = i - n*EE;
    int s = n % SS;
    h[i] = tok[(size_t)ids[n]*EE + e] + pos[(size_t)s*EE + e];
}

// ---------------- router ----------------
__global__ void router_kernel(const float* __restrict__ h,
                              const float* __restrict__ w1, const float* __restrict__ b1,
                              const float* __restrict__ w2, const float* __restrict__ b2,
                              float* __restrict__ rlog, int* __restrict__ dep) {
    int n = blockIdx.x;
    int tid = threadIdx.x;   // 128 threads
    __shared__ float r1[RH];
    __shared__ float lg[MAXD];
    const float* hr = h + (size_t)n*EE;
    {
        const float4* hv = reinterpret_cast<const float4*>(hr);
        const float4* wv = reinterpret_cast<const float4*>(w1 + (size_t)tid*EE);
        float acc = b1[tid];
        #pragma unroll 4
        for (int e = 0; e < EE/4; e++) {
            float4 a = hv[e], b = wv[e];
            acc += a.x*b.x + a.y*b.y + a.z*b.z + a.w*b.w;
        }
        r1[tid] = fmaxf(acc, 0.f);
    }
    __syncthreads();
    if (tid < MAXD) {
        float acc = b2[tid];
        const float* wr = w2 + tid*RH;
        #pragma unroll 8
        for (int j = 0; j < RH; j++) acc += r1[j]*wr[j];
        lg[tid] = acc;
        rlog[n*MAXD + tid] = acc;
    }
    __syncthreads();
    if (tid == 0) {
        int best = 0; float bv = lg[0];
        #pragma unroll
        for (int m = 1; m < MAXD; m++) if (lg[m] > bv) { bv = lg[m]; best = m; }
        dep[n] = best + 1;
    }
}

// ---------------- layernorm per token ----------------
__global__ void ln_kernel(const float* __restrict__ x,
                          const float* __restrict__ g, const float* __restrict__ b,
                          float* __restrict__ y) {
    int n = blockIdx.x, tid = threadIdx.x;   // 256 threads
    __shared__ float red[256];
    __shared__ float s_mu, s_rstd;
    const float* xr = x + (size_t)n*EE;
    float s = 0.f;
    for (int e = tid; e < EE; e += 256) s += xr[e];
    red[tid] = s; __syncthreads();
    for (int o = 128; o > 0; o >>= 1) { if (tid < o) red[tid] += red[tid+o]; __syncthreads(); }
    if (tid == 0) s_mu = red[0] * (1.f/EE);
    __syncthreads();
    float mu = s_mu;
    float v = 0.f;
    for (int e = tid; e < EE; e += 256) { float d = xr[e]-mu; v += d*d; }
    red[tid] = v; __syncthreads();
    for (int o = 128; o > 0; o >>= 1) { if (tid < o) red[tid] += red[tid+o]; __syncthreads(); }
    if (tid == 0) s_rstd = rsqrtf(red[0]*(1.f/EE) + 1e-5f);
    __syncthreads();
    float rstd = s_rstd;
    float* yr = y + (size_t)n*EE;
    for (int e = tid; e < EE; e += 256) yr[e] = (xr[e]-mu)*rstd*g[e] + b[e];
}

// ---------------- tf32 helpers ----------------
__device__ __forceinline__ void split_tf32(float x, uint32_t& hi, uint32_t& lo) {
    uint32_t h;
    asm("cvt.rna.tf32.f32 %0, %1;" : "=r"(h) : "f"(x));
    float lf = x - __uint_as_float(h);
    uint32_t l;
    asm("cvt.rna.tf32.f32 %0, %1;" : "=r"(l) : "f"(lf));
    hi = h; lo = l;
}

__device__ __forceinline__ void mma_tf32(float* d, const uint32_t* a, const uint32_t* b) {
    asm volatile(
        "mma.sync.aligned.m16n8k8.row.col.f32.tf32.tf32.f32 "
        "{%0,%1,%2,%3}, {%4,%5,%6,%7}, {%8,%9}, {%0,%1,%2,%3};"
        : "+f"(d[0]), "+f"(d[1]), "+f"(d[2]), "+f"(d[3])
        : "r"(a[0]), "r"(a[1]), "r"(a[2]), "r"(a[3]),
          "r"(b[0]), "r"(b[1]));
}

// ---------------- bf16 helpers (lm_head only) ----------------
__device__ __forceinline__ void split_bf16(float2 v, uint32_t& hi, uint32_t& lo) {
    uint32_t ux = __float_as_uint(v.x);
    uint32_t uy = __float_as_uint(v.y);
    uint32_t hx = ux & 0xFFFF0000u;
    uint32_t hy = uy & 0xFFFF0000u;
    hi = (hx >> 16) | hy;                       // x -> low half, y -> high half
    float lx = v.x - __uint_as_float(hx);
    float ly = v.y - __uint_as_float(hy);
    asm("cvt.rn.bf16x2.f32 %0, %1, %2;" : "=r"(lo) : "f"(ly), "f"(lx));
}

__device__ __forceinline__ void mma_bf16(float* d, const uint32_t* a, const uint32_t* b) {
    asm volatile(
        "mma.sync.aligned.m16n8k16.row.col.f32.bf16.bf16.f32 "
        "{%0,%1,%2,%3}, {%4,%5,%6,%7}, {%8,%9}, {%0,%1,%2,%3};"
        : "+f"(d[0]), "+f"(d[1]), "+f"(d[2]), "+f"(d[3])
        : "r"(a[0]), "r"(a[1]), "r"(a[2]), "r"(a[3]),
          "r"(b[0]), "r"(b[1]));
}

__device__ __forceinline__ void cp_async16(uint32_t dst, const void* src, bool pred) {
    int sz = pred ? 16 : 0;
    asm volatile("cp.async.ca.shared.global [%0], [%1], 16, %2;\n"
                 :: "r"(dst), "l"(src), "r"(sz));
}

// ---------------- GEMM NT via 3xTF32 mma + cp.async 2-stage pipeline ----------------
// C[M,Nn] (op)= act(A[M,K] * W[Nn,K]^T + bias)
// EPI: 0 = store, 1 = gelu + store, 2 = accumulate. M mult of 128, K mult of 32.
// BN: 128 (large-N gemms) or 64 (wo/w2: doubles grid to fix SM starvation).
#define TILE_A_B (128*36*4)                        // A tile bytes
#define TW_B(BN) ((BN)*36*4)                       // W tile bytes
#define GEMM_SMEM_BN(BN) (2*(TILE_A_B + TW_B(BN))) // 2 stages
template <int EPI, int BN>
__global__ __launch_bounds__(256, 2)
void gemm3x(const float* __restrict__ A, const float* __restrict__ W,
            const float* __restrict__ bias, float* __restrict__ C,
            int Nn, int K) {
    constexpr int NFRAG = BN / 32;        // per-warp n fragments (of 8)
    constexpr int WROWS = BN / 32;        // W loader row groups
    extern __shared__ float smem_f[];
    uint32_t sbase;
    asm("{ .reg .u64 t; cvta.to.shared.u64 t, %1; cvt.u32.u64 %0, t; }"
        : "=r"(sbase) : "l"(smem_f));

    const uint32_t STAGE_B = TILE_A_B + TW_B(BN);

    int tid = threadIdx.x;
    int m0 = blockIdx.y * 128;
    int n0 = blockIdx.x * BN;
    int warp = tid >> 5, lane = tid & 31;
    int wm = (warp & 1) * 64;            // warp tile 64(m) x BN/4(n)
    int wn = (warp >> 1) * (BN/4);
    int g = lane >> 2, t = lane & 3;

    float acc[4][NFRAG][4];
    #pragma unroll
    for (int mf = 0; mf < 4; mf++)
        #pragma unroll
        for (int nf = 0; nf < NFRAG; nf++)
            #pragma unroll
            for (int i = 0; i < 4; i++) acc[mf][nf][i] = 0.f;

    int lrow = tid >> 3;          // 0..31
    int lk4  = (tid & 7) * 4;     // 0,4,...,28

    const int nk = K >> 5;

    auto load_stage = [&](int st, int k0) {
        uint32_t baseA = sbase + (uint32_t)st * STAGE_B;
        uint32_t baseW = baseA + TILE_A_B;
        #pragma unroll
        for (int p = 0; p < 4; p++) {
            int r = lrow + p * 32;
            uint32_t off = (uint32_t)(r*36 + lk4) * 4u;
            cp_async16(baseA + off, &A[(size_t)(m0 + r)*K + k0 + lk4], true);
        }
        #pragma unroll
        for (int p = 0; p < WROWS; p++) {
            int r = lrow + p * 32;
            uint32_t off = (uint32_t)(r*36 + lk4) * 4u;
            int nn = n0 + r;
            int nnc = nn < Nn ? nn : (Nn - 1);
            cp_async16(baseW + off, &W[(size_t)nnc*K + k0 + lk4], nn < Nn);
        }
    };

    load_stage(0, 0);
    asm volatile("cp.async.commit_group;");

    for (int i = 0; i < nk; i++) {
        if (i + 1 < nk) {
            load_stage((i + 1) & 1, (i + 1) << 5);
            asm volatile("cp.async.commit_group;");
            asm volatile("cp.async.wait_group 1;");
        } else {
            asm volatile("cp.async.wait_group 0;");
        }
        __syncthreads();

        int st = i & 1;
        float (*sA)[36] = (float(*)[36])(smem_f + (size_t)st * (STAGE_B/4));
        float (*sW)[36] = (float(*)[36])(smem_f + (size_t)st * (STAGE_B/4) + 128 * 36);

        #pragma unroll
        for (int ks = 0; ks < 4; ks++) {
            int kk = ks * 8;
            uint32_t ahi[4][4], alo[4][4], bhi[NFRAG][2], blo[NFRAG][2];
            #pragma unroll
            for (int mf = 0; mf < 4; mf++) {
                int mr = wm + mf*16;
                split_tf32(sA[mr + g    ][kk + t    ], ahi[mf][0], alo[mf][0]);
                split_tf32(sA[mr + g + 8][kk + t    ], ahi[mf][1], alo[mf][1]);
                split_tf32(sA[mr + g    ][kk + t + 4], ahi[mf][2], alo[mf][2]);
                split_tf32(sA[mr + g + 8][kk + t + 4], ahi[mf][3], alo[mf][3]);
            }
            #pragma unroll
            for (int nf = 0; nf < NFRAG; nf++) {
                int nr = wn + nf*8;
                split_tf32(sW[nr + g][kk + t    ], bhi[nf][0], blo[nf][0]);
                split_tf32(sW[nr + g][kk + t + 4], bhi[nf][1], blo[nf][1]);
            }
            #pragma unroll
            for (int mf = 0; mf < 4; mf++)
                #pragma unroll
                for (int nf = 0; nf < NFRAG; nf++) {
                    mma_tf32(acc[mf][nf], ahi[mf], bhi[nf]);
                    mma_tf32(acc[mf][nf], alo[mf], bhi[nf]);
                    mma_tf32(acc[mf][nf], ahi[mf], blo[nf]);
                }
        }
        __syncthreads();
    }

    #pragma unroll
    for (int mf = 0; mf < 4; mf++) {
        #pragma unroll
        for (int nf = 0; nf < NFRAG; nf++) {
            #pragma unroll
            for (int i = 0; i < 4; i++) {
                int m = m0 + wm + mf*16 + g + (i >> 1) * 8;
                int n = n0 + wn + nf*8 + t*2 + (i & 1);
                if (n < Nn) {
                    float v = acc[mf][nf][i] + (bias ? bias[n] : 0.f);
                    if (EPI == 1) v = 0.5f*v*(1.0f + erff(v*0.70710678118654752f));
                    size_t ci = (size_t)m*Nn + n;
                    if (EPI == 2) C[ci] += v; else C[ci] = v;
                }
            }
        }
    }
}

// ---------------- lm_head GEMM: bf16x2 3-term emulation (2x tensor rate) ----------------
// C[M,Nn] = A[M,K] * W[Nn,K]^T (no bias). Grid: x = m-tile, y = n-tile (W reuse in L2).
#define GEMM_SMEM_LMH (2*(TILE_A_B + TILE_A_B))
__global__ __launch_bounds__(256, 2)
void gemm_lmh(const float* __restrict__ A, const float* __restrict__ W,
              float* __restrict__ C, int Nn, int K) {
    extern __shared__ float smem_f[];
    uint32_t sbase;
    asm("{ .reg .u64 t; cvta.to.shared.u64 t, %1; cvt.u32.u64 %0, t; }"
        : "=r"(sbase) : "l"(smem_f));

    int tid = threadIdx.x;
    int m0 = blockIdx.x * 128;     // transposed grid: x = m-tile
    int n0 = blockIdx.y * 128;     //                  y = n-tile
    int warp = tid >> 5, lane = tid & 31;
    int wm = (warp & 1) * 64;
    int wn = (warp >> 1) * 32;
    int g = lane >> 2, t = lane & 3;

    float acc[4][4][4];
    #pragma unroll
    for (int mf = 0; mf < 4; mf++)
        #pragma unroll
        for (int nf = 0; nf < 4; nf++)
            #pragma unroll
            for (int i = 0; i < 4; i++) acc[mf][nf][i] = 0.f;

    int lrow = tid >> 3;
    int lk4  = (tid & 7) * 4;
    const int nk = K >> 5;

    auto load_stage = [&](int st, int k0) {
        uint32_t baseA = sbase + (uint32_t)st * 2u * TILE_A_B;
        uint32_t baseW = baseA + TILE_A_B;
        #pragma unroll
        for (int p = 0; p < 4; p++) {
            int r = lrow + p * 32;
            uint32_t off = (uint32_t)(r*36 + lk4) * 4u;
            cp_async16(baseA + off, &A[(size_t)(m0 + r)*K + k0 + lk4], true);
            int nn = n0 + r;
            int nnc = nn < Nn ? nn : (Nn - 1);
            cp_async16(baseW + off, &W[(size_t)nnc*K + k0 + lk4], nn < Nn);
        }
    };

    load_stage(0, 0);
    asm volatile("cp.async.commit_group;");

    for (int i = 0; i < nk; i++) {
        if (i + 1 < nk) {
            load_stage((i + 1) & 1, (i + 1) << 5);
            asm volatile("cp.async.commit_group;");
            asm volatile("cp.async.wait_group 1;");
        } else {
            asm volatile("cp.async.wait_group 0;");
        }
        __syncthreads();

        int st = i & 1;
        float (*sA)[36] = (float(*)[36])(smem_f + (size_t)st * 2 * 128 * 36);
        float (*sW)[36] = (float(*)[36])(smem_f + (size_t)st * 2 * 128 * 36 + 128 * 36);

        #pragma unroll
        for (int ks = 0; ks < 2; ks++) {          // two k=16 steps per 32-tile
            int kk = ks * 16;
            int t2 = 2 * t;
            uint32_t ahi[4][4], alo[4][4], bhi[4][2], blo[4][2];
            #pragma unroll
            for (int mf = 0; mf < 4; mf++) {
                int mr = wm + mf*16;
                float2 f;
                f = *reinterpret_cast<const float2*>(&sA[mr + g    ][kk + t2    ]);
                split_bf16(f, ahi[mf][0], alo[mf][0]);
                f = *reinterpret_cast<const float2*>(&sA[mr + g + 8][kk + t2    ]);
                split_bf16(f, ahi[mf][1], alo[mf][1]);
                f = *reinterpret_cast<const float2*>(&sA[mr + g    ][kk + t2 + 8]);
                split_bf16(f, ahi[mf][2], alo[mf][2]);
                f = *reinterpret_cast<const float2*>(&sA[mr + g + 8][kk + t2 + 8]);
                split_bf16(f, ahi[mf][3], alo[mf][3]);
            }
            #pragma unroll
            for (int nf = 0; nf < 4; nf++) {
                int nr = wn + nf*8;
                float2 f;
                f = *reinterpret_cast<const float2*>(&sW[nr + g][kk + t2    ]);
                split_bf16(f, bhi[nf][0], blo[nf][0]);
                f = *reinterpret_cast<const float2*>(&sW[nr + g][kk + t2 + 8]);
                split_bf16(f, bhi[nf][1], blo[nf][1]);
            }
            #pragma unroll
            for (int mf = 0; mf < 4; mf++)
                #pragma unroll
                for (int nf = 0; nf < 4; nf++) {
                    mma_bf16(acc[mf][nf], ahi[mf], bhi[nf]);
                    mma_bf16(acc[mf][nf], alo[mf], bhi[nf]);
                    mma_bf16(acc[mf][nf], ahi[mf], blo[nf]);
                }
        }
        __syncthreads();
    }

    #pragma unroll
    for (int mf = 0; mf < 4; mf++) {
        #pragma unroll
        for (int nf = 0; nf < 4; nf++) {
            #pragma unroll
            for (int i = 0; i < 4; i++) {
                int m = m0 + wm + mf*16 + g + (i >> 1) * 8;
                int n = n0 + wn + nf*8 + t*2 + (i & 1);
                if (n < Nn)
                    C[(size_t)m*Nn + n] = acc[mf][nf][i];
            }
        }
    }
}

// ---------------- tiled attention: 64 q-rows per block, online softmax ----------------
__global__ __launch_bounds__(256, 2)
void attn_tile_kernel(const float* __restrict__ qkv, const int* __restrict__ dep,
                      int depth, float* __restrict__ out) {
    extern __shared__ float sm[];
    float (*Qs)[65] = (float(*)[65])(sm);
    float (*Ks)[65] = (float(*)[65])(sm + 64*65);
    float (*Vs)[65] = (float(*)[65])(sm + 2*64*65);
    float (*Ps)[65] = (float(*)[65])(sm + 3*64*65);
    float* m_s  = sm + 4*64*65;
    float* l_s  = m_s + 64;
    float* al_s = l_s + 64;
    int*   dq_s = (int*)(al_s + 64);
    int*   dk_s = dq_s + 64;

    int qt = blockIdx.x, h = blockIdx.y, b = blockIdx.z;
    int q0 = qt * 64;
    int tid = threadIdx.x;
    int tx = tid & 15, ty = tid >> 4;

    {
        int d4 = (tid & 15) * 4, q = tid >> 4;
        #pragma unroll
        for (int p = 0; p < 4; p++) {
            int qq = q + p*16;
            float4 v = *reinterpret_cast<const float4*>(
                &qkv[((size_t)b*SS + q0 + qq)*QKVW + h*DD + d4]);
            Qs[qq][d4+0] = v.x; Qs[qq][d4+1] = v.y; Qs[qq][d4+2] = v.z; Qs[qq][d4+3] = v.w;
        }
    }
    if (tid < 64) {
        dq_s[tid] = (dep[b*SS + q0 + tid] >= depth) ? 1 : 0;
        m_s[tid] = -1e30f;
        l_s[tid] = 0.f;
    }

    float O[4][4];
    #pragma unroll
    for (int i = 0; i < 4; i++)
        #pragma unroll
        for (int j = 0; j < 4; j++) O[i][j] = 0.f;

    for (int k0 = 0; k0 < SS; k0 += 64) {
        __syncthreads();
        {
            int d4 = (tid & 15) * 4, j = tid >> 4;
            #pragma unroll
            for (int p = 0; p < 4; p++) {
                int jj = j + p*16;
                size_t row = ((size_t)b*SS + k0 + jj)*QKVW + h*DD;
                float4 kv = *reinterpret_cast<const float4*>(&qkv[row + EE + d4]);
                Ks[jj][d4+0] = kv.x; Ks[jj][d4+1] = kv.y; Ks[jj][d4+2] = kv.z; Ks[jj][d4+3] = kv.w;
                float4 vv = *reinterpret_cast<const float4*>(&qkv[row + 2*EE + d4]);
                Vs[jj][d4+0] = vv.x; Vs[jj][d4+1] = vv.y; Vs[jj][d4+2] = vv.z; Vs[jj][d4+3] = vv.w;
            }
        }
        if (tid < 64) dk_s[tid] = (dep[b*SS + k0 + tid] >= depth) ? 1 : 0;
        __syncthreads();

        float sacc[4][4];
        #pragma unroll
        for (int i = 0; i < 4; i++)
            #pragma unroll
            for (int j = 0; j < 4; j++) sacc[i][j] = 0.f;
        #pragma unroll 8
        for (int d = 0; d < 64; d++) {
            float a[4], bb[4];
            #pragma unroll
            for (int i = 0; i < 4; i++) a[i] = Qs[ty*4+i][d];
            #pragma unroll
            for (int j = 0; j < 4; j++) bb[j] = Ks[tx*4+j][d];
            #pragma unroll
            for (int i = 0; i < 4; i++)
                #pragma unroll
                for (int j = 0; j < 4; j++) sacc[i][j] += a[i]*bb[j];
        }
        #pragma unroll
        for (int i = 0; i < 4; i++) {
            int row = ty*4 + i;
            int rowg = q0 + row;
            #pragma unroll
            for (int j = 0; j < 4; j++) {
                int col = tx*4 + j;
                int colg = k0 + col;
                float msk = (colg <= rowg && dq_s[row] && dk_s[col]) ? 1.f : 0.f;
                Ps[row][col] = sacc[i][j]*0.125f + msk;
            }
        }
        __syncthreads();

        {
            int rid = tid >> 2, sub = tid & 3;
            float mx = -1e30f;
            #pragma unroll
            for (int jj = 0; jj < 16; jj++) mx = fmaxf(mx, Ps[rid][sub*16+jj]);
            mx = fmaxf(mx, __shfl_xor_sync(0xffffffff, mx, 1));
            mx = fmaxf(mx, __shfl_xor_sync(0xffffffff, mx, 2));
            float mold = m_s[rid];
            float mnew = fmaxf(mold, mx);
            float sum = 0.f;
            #pragma unroll
            for (int jj = 0; jj < 16; jj++) {
                float p = __expf(Ps[rid][sub*16+jj] - mnew);
                Ps[rid][sub*16+jj] = p;
                sum += p;
            }
            sum += __shfl_xor_sync(0xffffffff, sum, 1);
            sum += __shfl_xor_sync(0xffffffff, sum, 2);
            if (sub == 0) {
                float alpha = __expf(mold - mnew);
                al_s[rid] = alpha;
                l_s[rid] = l_s[rid]*alpha + sum;
                m_s[rid] = mnew;
            }
        }
        __syncthreads();

        float alr[4];
        #pragma unroll
        for (int i = 0; i < 4; i++) alr[i] = al_s[ty*4+i];
        #pragma unroll
        for (int i = 0; i < 4; i++)
            #pragma unroll
            for (int j = 0; j < 4; j++) O[i][j] *= alr[i];
        #pragma unroll 8
        for (int k = 0; k < 64; k++) {
            float a[4], bb[4];
            #pragma unroll
            for (int i = 0; i < 4; i++) a[i] = Ps[ty*4+i][k];
            #pragma unroll
            for (int j = 0; j < 4; j++) bb[j] = Vs[k][tx*4+j];
            #pragma unroll
            for (int i = 0; i < 4; i++)
                #pragma unroll
                for (int j = 0; j < 4; j++) O[i][j] += a[i]*bb[j];
        }
    }
    __syncthreads();

    #pragma unroll
    for (int i = 0; i < 4; i++) {
        int row = ty*4 + i;
        float inv = 1.f / l_s[row];
        #pragma unroll
        for (int j = 0; j < 4; j++) {
            out[((size_t)b*SS + q0 + row)*EE + h*DD + tx*4 + j] = O[i][j]*inv;
        }
    }
}

// ---------------- router aux loss ----------------
__global__ void loss_kernel(const float* __restrict__ rlog, const int* __restrict__ dep,
                            float* __restrict__ loss) {
    int tid = threadIdx.x;  // 1024
    __shared__ float red[1024];
    float p[MAXD] = {0,0,0,0};
    float ds = 0.f;
    for (int n = tid; n < NN; n += 1024) {
        float l0 = rlog[n*4+0], l1 = rlog[n*4+1], l2 = rlog[n*4+2], l3 = rlog[n*4+3];
        float m = fmaxf(fmaxf(l0,l1), fmaxf(l2,l3));
        float e0 = expf(l0-m), e1 = expf(l1-m), e2 = expf(l2-m), e3 = expf(l3-m);
        float inv = 1.f/(e0+e1+e2+e3);
        p[0] += e0*inv; p[1] += e1*inv; p[2] += e2*inv; p[3] += e3*inv;
        ds += (float)dep[n];
    }
    float sums[5];
    float vals[5] = {p[0], p[1], p[2], p[3], ds};
    for (int v = 0; v < 5; v++) {
        red[tid] = vals[v]; __syncthreads();
        for (int o = 512; o > 0; o >>= 1) { if (tid < o) red[tid] += red[tid+o]; __syncthreads(); }
        sums[v] = red[0]; __syncthreads();
    }
    if (tid == 0) {
        const float u = 1.f/MAXD;
        float lb = 0.f;
        for (int m = 0; m < MAXD; m++) {
            float mp = sums[m] / (float)NN;
            lb += u * (logf(u) - logf(mp));
        }
        lb /= MAXD;
        float sparsity = (sums[4] / (float)NN) / MAXD;
        loss[0] = 0.01f*lb + 0.001f*sparsity;
    }
}

// ---------------- output tail ----------------
__global__ void finalize_kernel(const int* __restrict__ dep, const float* __restrict__ rlog,
                                const float* __restrict__ loss, float* __restrict__ out) {
    int i = blockIdx.x * blockDim.x + threadIdx.x;
    size_t base = (size_t)NN * VV;
    if (i < NN) out[base + i] = (float)dep[i];
    if (i == 0) out[base + NN] = loss[0];
    if (i < NN*MAXD) out[base + NN + 1 + i] = rlog[i];
}

// ---------------- host orchestration ----------------
extern "C" void kernel_launch(void* const* d_in, const int* in_sizes, int n_in,
                              void* d_out, int out_size) {
    const int*   ids  = (const int*)  d_in[0];
    const float* tok  = (const float*)d_in[1];
    const float* pos  = (const float*)d_in[2];
    const float* rw1  = (const float*)d_in[3];
    const float* rb1  = (const float*)d_in[4];
    const float* rw2  = (const float*)d_in[5];
    const float* rb2  = (const float*)d_in[6];
    const float* wqkv = (const float*)d_in[7];
    const float* bqkv = (const float*)d_in[8];
    const float* wo   = (const float*)d_in[9];
    const float* bo   = (const float*)d_in[10];
    const float* ln1g = (const float*)d_in[11];
    const float* ln1b = (const float*)d_in[12];
    const float* ln2g = (const float*)d_in[13];
    const float* ln2b = (const float*)d_in[14];
    const float* w1   = (const float*)d_in[15];
    const float* b1   = (const float*)d_in[16];
    const float* w2   = (const float*)d_in[17];
    const float* b2   = (const float*)d_in[18];
    const float* lnfg = (const float*)d_in[19];
    const float* lnfb = (const float*)d_in[20];
    const float* lmh  = (const float*)d_in[21];
    float* out = (float*)d_out;

    float *ph, *phn, *pqkv, *pattn, *pffa, *prl, *ploss;
    int* pdep;
    cudaGetSymbolAddress((void**)&ph,    g_h);
    cudaGetSymbolAddress((void**)&phn,   g_hn);
    cudaGetSymbolAddress((void**)&pqkv,  g_qkv);
    cudaGetSymbolAddress((void**)&pattn, g_attn);
    cudaGetSymbolAddress((void**)&pffa,  g_ffa);
    cudaGetSymbolAddress((void**)&prl,   g_rlog);
    cudaGetSymbolAddress((void**)&ploss, g_loss);
    cudaGetSymbolAddress((void**)&pdep,  g_dep);

    static const int ATTN_SMEM = (4*64*65 + 3*64) * sizeof(float) + 2*64*sizeof(int);
    cudaFuncSetAttribute(attn_tile_kernel, cudaFuncAttributeMaxDynamicSharedMemorySize, ATTN_SMEM);
    cudaFuncSetAttribute((gemm3x<0,128>), cudaFuncAttributeMaxDynamicSharedMemorySize, GEMM_SMEM_BN(128));
    cudaFuncSetAttribute((gemm3x<1,128>), cudaFuncAttributeMaxDynamicSharedMemorySize, GEMM_SMEM_BN(128));
    cudaFuncSetAttribute((gemm3x<2,64>),  cudaFuncAttributeMaxDynamicSharedMemorySize, GEMM_SMEM_BN(64));
    cudaFuncSetAttribute(gemm_lmh,        cudaFuncAttributeMaxDynamicSharedMemorySize, GEMM_SMEM_LMH);

    embed_kernel<<<(NN*EE + 255)/256, 256>>>(ids, tok, pos, ph);
    router_kernel<<<NN, RH>>>(ph, rw1, rb1, rw2, rb2, prl, pdep);

    for (int depth = 1; depth <= MAXD; depth++) {
        int li = depth - 1;
        ln_kernel<<<NN, 256>>>(ph, ln1g + li*EE, ln1b + li*EE, phn);
        {
            dim3 g(QKVW/128, NN/128);
            gemm3x<0,128><<<g, 256, GEMM_SMEM_BN(128)>>>(phn, wqkv + (size_t)li*QKVW*EE, bqkv + li*QKVW, pqkv, QKVW, EE);
        }
        attn_tile_kernel<<<dim3(SS/64, HH, BB), 256, ATTN_SMEM>>>(pqkv, pdep, depth, pattn);
        {
            dim3 g(EE/64, NN/128);     // BN=64: 192 CTAs
            gemm3x<2,64><<<g, 256, GEMM_SMEM_BN(64)>>>(pattn, wo + (size_t)li*EE*EE, bo + li*EE, ph, EE, EE);
        }
        ln_kernel<<<NN, 256>>>(ph, ln2g + li*EE, ln2b + li*EE, phn);
        {
            dim3 g(II/128, NN/128);
            gemm3x<1,128><<<g, 256, GEMM_SMEM_BN(128)>>>(phn, w1 + (size_t)li*II*EE, b1 + li*II, pffa, II, EE);
        }
        {
            dim3 g(EE/64, NN/128);     // BN=64: 192 CTAs (was 96 -> SM starvation)
            gemm3x<2,64><<<g, 256, GEMM_SMEM_BN(64)>>>(pffa, w2 + (size_t)li*EE*II, b2 + li*EE, ph, EE, II);
        }
    }

    ln_kernel<<<NN, 256>>>(ph, lnfg, lnfb, phn);
    {
        dim3 g(NN/128, (VV + 127)/128);   // x = m-tile, y = n-tile (W reuse in L2)
        gemm_lmh<<<g, 256, GEMM_SMEM_LMH>>>(phn, lmh, out, VV, EE);
    }

    loss_kernel<<<1, 1024>>>(prl, pdep, ploss);

    long long full = (long long)NN*VV + NN + 1 + (long long)NN*MAXD;
    if ((long long)out_size >= full)
        finalize_kernel<<<(NN*MAXD + 255)/256, 256>>>(pdep, prl, ploss, out);
}

// round 11
// speedup vs baseline: 1.0407x; 1.0407x over previous
#include <cuda_runtime.h>
#include <cuda_bf16.h>
#include <math.h>
#include <stdint.h>

// ---------------- problem constants ----------------
#define BB 2
#define SS 1024
#define NN (BB*SS)          // 2048 tokens
#define EE 768
#define HH 12
#define DD 64
#define II 3072
#define LL 4
#define RH 128
#define MAXD 4
#define VV 50257
#define QKVW (3*EE)         // 2304

// ---------------- scratch (device globals; no allocation allowed) ----------------
__device__ float g_h   [NN*EE];
__device__ float g_hn  [NN*EE];
__device__ float g_qkv [NN*QKVW];   // also reused as 2x split-K partial buffers (wo/w2)
__device__ float g_attn[NN*EE];
__device__ float g_ffa [NN*II];
__device__ float g_rlog[NN*MAXD];
__device__ int   g_dep [NN];
__device__ float g_loss[1];

// ---------------- embedding ----------------
__global__ void embed_kernel(const int* __restrict__ ids,
                             const float* __restrict__ tok,
                             const float* __restrict__ pos,
                             float* __restrict__ h) {
    int i = blockIdx.x * blockDim.x + threadIdx.x;
    if (i >= NN*EE) return;
    int n = i / EE, e = i - n*EE;
    int s = n % SS;
    h[i] = tok[(size_t)ids[n]*EE + e] + pos[(size_t)s*EE + e];
}

// ---------------- router ----------------
__global__ void router_kernel(const float* __restrict__ h,
                              const float* __restrict__ w1, const float* __restrict__ b1,
                              const float* __restrict__ w2, const float* __restrict__ b2,
                              float* __restrict__ rlog, int* __restrict__ dep) {
    int n = blockIdx.x;
    int tid = threadIdx.x;   // 128 threads
    __shared__ float r1[RH];
    __shared__ float lg[MAXD];
    const float* hr = h + (size_t)n*EE;
    {
        const float4* hv = reinterpret_cast<const float4*>(hr);
        const float4* wv = reinterpret_cast<const float4*>(w1 + (size_t)tid*EE);
        float acc = b1[tid];
        #pragma unroll 4
        for (int e = 0; e < EE/4; e++) {
            float4 a = hv[e], b = wv[e];
            acc += a.x*b.x + a.y*b.y + a.z*b.z + a.w*b.w;
        }
        r1[tid] = fmaxf(acc, 0.f);
    }
    __syncthreads();
    if (tid < MAXD) {
        float acc = b2[tid];
        const float* wr = w2 + tid*RH;
        #pragma unroll 8
        for (int j = 0; j < RH; j++) acc += r1[j]*wr[j];
        lg[tid] = acc;
        rlog[n*MAXD + tid] = acc;
    }
    __syncthreads();
    if (tid == 0) {
        int best = 0; float bv = lg[0];
        #pragma unroll
        for (int m = 1; m < MAXD; m++) if (lg[m] > bv) { bv = lg[m]; best = m; }
        dep[n] = best + 1;
    }
}

// ---------------- layernorm per token ----------------
__global__ void ln_kernel(const float* __restrict__ x,
                          const float* __restrict__ g, const float* __restrict__ b,
                          float* __restrict__ y) {
    int n = blockIdx.x, tid = threadIdx.x;   // 256 threads
    __shared__ float red[256];
    __shared__ float s_mu, s_rstd;
    const float* xr = x + (size_t)n*EE;
    float s = 0.f;
    for (int e = tid; e < EE; e += 256) s += xr[e];
    red[tid] = s; __syncthreads();
    for (int o = 128; o > 0; o >>= 1) { if (tid < o) red[tid] += red[tid+o]; __syncthreads(); }
    if (tid == 0) s_mu = red[0] * (1.f/EE);
    __syncthreads();
    float mu = s_mu;
    float v = 0.f;
    for (int e = tid; e < EE; e += 256) { float d = xr[e]-mu; v += d*d; }
    red[tid] = v; __syncthreads();
    for (int o = 128; o > 0; o >>= 1) { if (tid < o) red[tid] += red[tid+o]; __syncthreads(); }
    if (tid == 0) s_rstd = rsqrtf(red[0]*(1.f/EE) + 1e-5f);
    __syncthreads();
    float rstd = s_rstd;
    float* yr = y + (size_t)n*EE;
    for (int e = tid; e < EE; e += 256) yr[e] = (xr[e]-mu)*rstd*g[e] + b[e];
}

// ---------------- split-K reduce: h += p0 + p1 ----------------
__global__ void add2_kernel(float* __restrict__ h,
                            const float* __restrict__ p0,
                            const float* __restrict__ p1) {
    int i = blockIdx.x * blockDim.x + threadIdx.x;
    if (i < NN*EE) h[i] += p0[i] + p1[i];
}

// ---------------- tf32 helpers ----------------
__device__ __forceinline__ void split_tf32(float x, uint32_t& hi, uint32_t& lo) {
    uint32_t h;
    asm("cvt.rna.tf32.f32 %0, %1;" : "=r"(h) : "f"(x));
    float lf = x - __uint_as_float(h);
    uint32_t l;
    asm("cvt.rna.tf32.f32 %0, %1;" : "=r"(l) : "f"(lf));
    hi = h; lo = l;
}

__device__ __forceinline__ void mma_tf32(float* d, const uint32_t* a, const uint32_t* b) {
    asm volatile(
        "mma.sync.aligned.m16n8k8.row.col.f32.tf32.tf32.f32 "
        "{%0,%1,%2,%3}, {%4,%5,%6,%7}, {%8,%9}, {%0,%1,%2,%3};"
        : "+f"(d[0]), "+f"(d[1]), "+f"(d[2]), "+f"(d[3])
        : "r"(a[0]), "r"(a[1]), "r"(a[2]), "r"(a[3]),
          "r"(b[0]), "r"(b[1]));
}

// ---------------- bf16 helpers (lm_head only) ----------------
__device__ __forceinline__ void split_bf16(float2 v, uint32_t& hi, uint32_t& lo) {
    uint32_t ux = __float_as_uint(v.x);
    uint32_t uy = __float_as_uint(v.y);
    uint32_t hx = ux & 0xFFFF0000u;
    uint32_t hy = uy & 0xFFFF0000u;
    hi = (hx >> 16) | hy;                       // x -> low half, y -> high half
    float lx = v.x - __uint_as_float(hx);
    float ly = v.y - __uint_as_float(hy);
    asm("cvt.rn.bf16x2.f32 %0, %1, %2;" : "=r"(lo) : "f"(ly), "f"(lx));
}

__device__ __forceinline__ void mma_bf16(float* d, const uint32_t* a, const uint32_t* b) {
    asm volatile(
        "mma.sync.aligned.m16n8k16.row.col.f32.bf16.bf16.f32 "
        "{%0,%1,%2,%3}, {%4,%5,%6,%7}, {%8,%9}, {%0,%1,%2,%3};"
        : "+f"(d[0]), "+f"(d[1]), "+f"(d[2]), "+f"(d[3])
        : "r"(a[0]), "r"(a[1]), "r"(a[2]), "r"(a[3]),
          "r"(b[0]), "r"(b[1]));
}

__device__ __forceinline__ void cp_async16(uint32_t dst, const void* src, bool pred) {
    int sz = pred ? 16 : 0;
    asm volatile("cp.async.ca.shared.global [%0], [%1], 16, %2;\n"
                 :: "r"(dst), "l"(src), "r"(sz));
}

// ---------------- GEMM NT via 3xTF32 mma + cp.async 2-stage pipeline ----------------
// C[M,Nn] (op)= act(A[M,K] * W[Nn,K]^T + bias),  M = 2048 rows always.
// EPI: 0 = store, 1 = gelu + store.
// Split-K: gridDim.z = P parts; part z covers K-range [z*K/P, (z+1)*K/P) and
// writes to C + z*2048*Nn (partial buffers). bias applied only on z==0.
#define TILE_B (128*36*4)            // one 128x36 fp32 tile in bytes
#define GEMM_SMEM (4*TILE_B)         // 2 stages x (A + W)
template <int EPI>
__global__ __launch_bounds__(256, 2)
void gemm3x(const float* __restrict__ A, const float* __restrict__ W,
            const float* __restrict__ bias, float* __restrict__ C,
            int Nn, int K) {
    extern __shared__ float smem_f[];
    uint32_t sbase;
    asm("{ .reg .u64 t; cvta.to.shared.u64 t, %1; cvt.u32.u64 %0, t; }"
        : "=r"(sbase) : "l"(smem_f));

    int tid = threadIdx.x;
    int m0 = blockIdx.y * 128;
    int n0 = blockIdx.x * 128;
    // split-K part
    int Kp = K / gridDim.z;
    int kbase = blockIdx.z * Kp;
    if (gridDim.z > 1) C += (size_t)blockIdx.z * (size_t)2048 * Nn;
    bool do_bias = (bias != nullptr) && (blockIdx.z == 0);

    int warp = tid >> 5, lane = tid & 31;
    int wm = (warp & 1) * 64;     // warp tile 64(m) x 32(n)
    int wn = (warp >> 1) * 32;
    int g = lane >> 2, t = lane & 3;

    float acc[4][4][4];
    #pragma unroll
    for (int mf = 0; mf < 4; mf++)
        #pragma unroll
        for (int nf = 0; nf < 4; nf++)
            #pragma unroll
            for (int i = 0; i < 4; i++) acc[mf][nf][i] = 0.f;

    int lrow = tid >> 3;          // 0..31
    int lk4  = (tid & 7) * 4;     // 0,4,...,28

    const int nk = Kp >> 5;

    auto load_stage = [&](int st, int k0) {
        uint32_t baseA = sbase + (uint32_t)st * 2u * TILE_B;
        uint32_t baseW = baseA + TILE_B;
        #pragma unroll
        for (int p = 0; p < 4; p++) {
            int r = lrow + p * 32;
            uint32_t off = (uint32_t)(r*36 + lk4) * 4u;
            cp_async16(baseA + off, &A[(size_t)(m0 + r)*K + kbase + k0 + lk4], true);
            int nn = n0 + r;
            int nnc = nn < Nn ? nn : (Nn - 1);
            cp_async16(baseW + off, &W[(size_t)nnc*K + kbase + k0 + lk4], nn < Nn);
        }
    };

    load_stage(0, 0);
    asm volatile("cp.async.commit_group;");

    for (int i = 0; i < nk; i++) {
        if (i + 1 < nk) {
            load_stage((i + 1) & 1, (i + 1) << 5);
            asm volatile("cp.async.commit_group;");
            asm volatile("cp.async.wait_group 1;");
        } else {
            asm volatile("cp.async.wait_group 0;");
        }
        __syncthreads();

        int st = i & 1;
        float (*sA)[36] = (float(*)[36])(smem_f + (size_t)st * 2 * 128 * 36);
        float (*sW)[36] = (float(*)[36])(smem_f + (size_t)st * 2 * 128 * 36 + 128 * 36);

        #pragma unroll
        for (int ks = 0; ks < 4; ks++) {
            int kk = ks * 8;
            uint32_t ahi[4][4], alo[4][4], bhi[4][2], blo[4][2];
            #pragma unroll
            for (int mf = 0; mf < 4; mf++) {
                int mr = wm + mf*16;
                split_tf32(sA[mr + g    ][kk + t    ], ahi[mf][0], alo[mf][0]);
                split_tf32(sA[mr + g + 8][kk + t    ], ahi[mf][1], alo[mf][1]);
                split_tf32(sA[mr + g    ][kk + t + 4], ahi[mf][2], alo[mf][2]);
                split_tf32(sA[mr + g + 8][kk + t + 4], ahi[mf][3], alo[mf][3]);
            }
            #pragma unroll
            for (int nf = 0; nf < 4; nf++) {
                int nr = wn + nf*8;
                split_tf32(sW[nr + g][kk + t    ], bhi[nf][0], blo[nf][0]);
                split_tf32(sW[nr + g][kk + t + 4], bhi[nf][1], blo[nf][1]);
            }
            #pragma unroll
            for (int mf = 0; mf < 4; mf++)
                #pragma unroll
                for (int nf = 0; nf < 4; nf++) {
                    mma_tf32(acc[mf][nf], ahi[mf], bhi[nf]);
                    mma_tf32(acc[mf][nf], alo[mf], bhi[nf]);
                    mma_tf32(acc[mf][nf], ahi[mf], blo[nf]);
                }
        }
        __syncthreads();
    }

    #pragma unroll
    for (int mf = 0; mf < 4; mf++) {
        #pragma unroll
        for (int nf = 0; nf < 4; nf++) {
            #pragma unroll
            for (int i = 0; i < 4; i++) {
                int m = m0 + wm + mf*16 + g + (i >> 1) * 8;
                int n = n0 + wn + nf*8 + t*2 + (i & 1);
                if (n < Nn) {
                    float v = acc[mf][nf][i] + (do_bias ? bias[n] : 0.f);
                    if (EPI == 1) v = 0.5f*v*(1.0f + erff(v*0.70710678118654752f));
                    C[(size_t)m*Nn + n] = v;
                }
            }
        }
    }
}

// ---------------- lm_head GEMM: bf16x2 3-term emulation (2x tensor rate) ----------------
// C[M,Nn] = A[M,K] * W[Nn,K]^T (no bias). Grid: x = m-tile, y = n-tile (W reuse in L2).
__global__ __launch_bounds__(256, 2)
void gemm_lmh(const float* __restrict__ A, const float* __restrict__ W,
              float* __restrict__ C, int Nn, int K) {
    extern __shared__ float smem_f[];
    uint32_t sbase;
    asm("{ .reg .u64 t; cvta.to.shared.u64 t, %1; cvt.u32.u64 %0, t; }"
        : "=r"(sbase) : "l"(smem_f));

    int tid = threadIdx.x;
    int m0 = blockIdx.x * 128;     // transposed grid: x = m-tile
    int n0 = blockIdx.y * 128;     //                  y = n-tile
    int warp = tid >> 5, lane = tid & 31;
    int wm = (warp & 1) * 64;
    int wn = (warp >> 1) * 32;
    int g = lane >> 2, t = lane & 3;

    float acc[4][4][4];
    #pragma unroll
    for (int mf = 0; mf < 4; mf++)
        #pragma unroll
        for (int nf = 0; nf < 4; nf++)
            #pragma unroll
            for (int i = 0; i < 4; i++) acc[mf][nf][i] = 0.f;

    int lrow = tid >> 3;
    int lk4  = (tid & 7) * 4;
    const int nk = K >> 5;

    auto load_stage = [&](int st, int k0) {
        uint32_t baseA = sbase + (uint32_t)st * 2u * TILE_B;
        uint32_t baseW = baseA + TILE_B;
        #pragma unroll
        for (int p = 0; p < 4; p++) {
            int r = lrow + p * 32;
            uint32_t off = (uint32_t)(r*36 + lk4) * 4u;
            cp_async16(baseA + off, &A[(size_t)(m0 + r)*K + k0 + lk4], true);
            int nn = n0 + r;
            int nnc = nn < Nn ? nn : (Nn - 1);
            cp_async16(baseW + off, &W[(size_t)nnc*K + k0 + lk4], nn < Nn);
        }
    };

    load_stage(0, 0);
    asm volatile("cp.async.commit_group;");

    for (int i = 0; i < nk; i++) {
        if (i + 1 < nk) {
            load_stage((i + 1) & 1, (i + 1) << 5);
            asm volatile("cp.async.commit_group;");
            asm volatile("cp.async.wait_group 1;");
        } else {
            asm volatile("cp.async.wait_group 0;");
        }
        __syncthreads();

        int st = i & 1;
        float (*sA)[36] = (float(*)[36])(smem_f + (size_t)st * 2 * 128 * 36);
        float (*sW)[36] = (float(*)[36])(smem_f + (size_t)st * 2 * 128 * 36 + 128 * 36);

        #pragma unroll
        for (int ks = 0; ks < 2; ks++) {          // two k=16 steps per 32-tile
            int kk = ks * 16;
            int t2 = 2 * t;
            uint32_t ahi[4][4], alo[4][4], bhi[4][2], blo[4][2];
            #pragma unroll
            for (int mf = 0; mf < 4; mf++) {
                int mr = wm + mf*16;
                float2 f;
                f = *reinterpret_cast<const float2*>(&sA[mr + g    ][kk + t2    ]);
                split_bf16(f, ahi[mf][0], alo[mf][0]);
                f = *reinterpret_cast<const float2*>(&sA[mr + g + 8][kk + t2    ]);
                split_bf16(f, ahi[mf][1], alo[mf][1]);
                f = *reinterpret_cast<const float2*>(&sA[mr + g    ][kk + t2 + 8]);
                split_bf16(f, ahi[mf][2], alo[mf][2]);
                f = *reinterpret_cast<const float2*>(&sA[mr + g + 8][kk + t2 + 8]);
                split_bf16(f, ahi[mf][3], alo[mf][3]);
            }
            #pragma unroll
            for (int nf = 0; nf < 4; nf++) {
                int nr = wn + nf*8;
                float2 f;
                f = *reinterpret_cast<const float2*>(&sW[nr + g][kk + t2    ]);
                split_bf16(f, bhi[nf][0], blo[nf][0]);
                f = *reinterpret_cast<const float2*>(&sW[nr + g][kk + t2 + 8]);
                split_bf16(f, bhi[nf][1], blo[nf][1]);
            }
            #pragma unroll
            for (int mf = 0; mf < 4; mf++)
                #pragma unroll
                for (int nf = 0; nf < 4; nf++) {
                    mma_bf16(acc[mf][nf], ahi[mf], bhi[nf]);
                    mma_bf16(acc[mf][nf], alo[mf], bhi[nf]);
                    mma_bf16(acc[mf][nf], ahi[mf], blo[nf]);
                }
        }
        __syncthreads();
    }

    #pragma unroll
    for (int mf = 0; mf < 4; mf++) {
        #pragma unroll
        for (int nf = 0; nf < 4; nf++) {
            #pragma unroll
            for (int i = 0; i < 4; i++) {
                int m = m0 + wm + mf*16 + g + (i >> 1) * 8;
                int n = n0 + wn + nf*8 + t*2 + (i & 1);
                if (n < Nn)
                    C[(size_t)m*Nn + n] = acc[mf][nf][i];
            }
        }
    }
}

// ---------------- tiled attention: 64 q-rows per block, online softmax ----------------
__global__ __launch_bounds__(256)
void attn_tile_kernel(const float* __restrict__ qkv, const int* __restrict__ dep,
                      int depth, float* __restrict__ out) {
    extern __shared__ float sm[];
    float (*Qs)[65] = (float(*)[65])(sm);
    float (*Ks)[65] = (float(*)[65])(sm + 64*65);
    float (*Vs)[65] = (float(*)[65])(sm + 2*64*65);
    float (*Ps)[65] = (float(*)[65])(sm + 3*64*65);
    float* m_s  = sm + 4*64*65;
    float* l_s  = m_s + 64;
    float* al_s = l_s + 64;
    int*   dq_s = (int*)(al_s + 64);
    int*   dk_s = dq_s + 64;

    int qt = blockIdx.x, h = blockIdx.y, b = blockIdx.z;
    int q0 = qt * 64;
    int tid = threadIdx.x;
    int tx = tid & 15, ty = tid >> 4;

    {
        int d4 = (tid & 15) * 4, q = tid >> 4;
        #pragma unroll
        for (int p = 0; p < 4; p++) {
            int qq = q + p*16;
            float4 v = *reinterpret_cast<const float4*>(
                &qkv[((size_t)b*SS + q0 + qq)*QKVW + h*DD + d4]);
            Qs[qq][d4+0] = v.x; Qs[qq][d4+1] = v.y; Qs[qq][d4+2] = v.z; Qs[qq][d4+3] = v.w;
        }
    }
    if (tid < 64) {
        dq_s[tid] = (dep[b*SS + q0 + tid] >= depth) ? 1 : 0;
        m_s[tid] = -1e30f;
        l_s[tid] = 0.f;
    }

    float O[4][4];
    #pragma unroll
    for (int i = 0; i < 4; i++)
        #pragma unroll
        for (int j = 0; j < 4; j++) O[i][j] = 0.f;

    for (int k0 = 0; k0 < SS; k0 += 64) {
        __syncthreads();
        {
            int d4 = (tid & 15) * 4, j = tid >> 4;
            #pragma unroll
            for (int p = 0; p < 4; p++) {
                int jj = j + p*16;
                size_t row = ((size_t)b*SS + k0 + jj)*QKVW + h*DD;
                float4 kv = *reinterpret_cast<const float4*>(&qkv[row + EE + d4]);
                Ks[jj][d4+0] = kv.x; Ks[jj][d4+1] = kv.y; Ks[jj][d4+2] = kv.z; Ks[jj][d4+3] = kv.w;
                float4 vv = *reinterpret_cast<const float4*>(&qkv[row + 2*EE + d4]);
                Vs[jj][d4+0] = vv.x; Vs[jj][d4+1] = vv.y; Vs[jj][d4+2] = vv.z; Vs[jj][d4+3] = vv.w;
            }
        }
        if (tid < 64) dk_s[tid] = (dep[b*SS + k0 + tid] >= depth) ? 1 : 0;
        __syncthreads();

        float sacc[4][4];
        #pragma unroll
        for (int i = 0; i < 4; i++)
            #pragma unroll
            for (int j = 0; j < 4; j++) sacc[i][j] = 0.f;
        #pragma unroll 8
        for (int d = 0; d < 64; d++) {
            float a[4], bb[4];
            #pragma unroll
            for (int i = 0; i < 4; i++) a[i] = Qs[ty*4+i][d];
            #pragma unroll
            for (int j = 0; j < 4; j++) bb[j] = Ks[tx*4+j][d];
            #pragma unroll
            for (int i = 0; i < 4; i++)
                #pragma unroll
                for (int j = 0; j < 4; j++) sacc[i][j] += a[i]*bb[j];
        }
        #pragma unroll
        for (int i = 0; i < 4; i++) {
            int row = ty*4 + i;
            int rowg = q0 + row;
            #pragma unroll
            for (int j = 0; j < 4; j++) {
                int col = tx*4 + j;
                int colg = k0 + col;
                float msk = (colg <= rowg && dq_s[row] && dk_s[col]) ? 1.f : 0.f;
                Ps[row][col] = sacc[i][j]*0.125f + msk;
            }
        }
        __syncthreads();

        {
            int rid = tid >> 2, sub = tid & 3;
            float mx = -1e30f;
            #pragma unroll
            for (int jj = 0; jj < 16; jj++) mx = fmaxf(mx, Ps[rid][sub*16+jj]);
            mx = fmaxf(mx, __shfl_xor_sync(0xffffffff, mx, 1));
            mx = fmaxf(mx, __shfl_xor_sync(0xffffffff, mx, 2));
            float mold = m_s[rid];
            float mnew = fmaxf(mold, mx);
            float sum = 0.f;
            #pragma unroll
            for (int jj = 0; jj < 16; jj++) {
                float p = __expf(Ps[rid][sub*16+jj] - mnew);
                Ps[rid][sub*16+jj] = p;
                sum += p;
            }
            sum += __shfl_xor_sync(0xffffffff, sum, 1);
            sum += __shfl_xor_sync(0xffffffff, sum, 2);
            if (sub == 0) {
                float alpha = __expf(mold - mnew);
                al_s[rid] = alpha;
                l_s[rid] = l_s[rid]*alpha + sum;
                m_s[rid] = mnew;
            }
        }
        __syncthreads();

        float alr[4];
        #pragma unroll
        for (int i = 0; i < 4; i++) alr[i] = al_s[ty*4+i];
        #pragma unroll
        for (int i = 0; i < 4; i++)
            #pragma unroll
            for (int j = 0; j < 4; j++) O[i][j] *= alr[i];
        #pragma unroll 8
        for (int k = 0; k < 64; k++) {
            float a[4], bb[4];
            #pragma unroll
            for (int i = 0; i < 4; i++) a[i] = Ps[ty*4+i][k];
            #pragma unroll
            for (int j = 0; j < 4; j++) bb[j] = Vs[k][tx*4+j];
            #pragma unroll
            for (int i = 0; i < 4; i++)
                #pragma unroll
                for (int j = 0; j < 4; j++) O[i][j] += a[i]*bb[j];
        }
    }
    __syncthreads();

    #pragma unroll
    for (int i = 0; i < 4; i++) {
        int row = ty*4 + i;
        float inv = 1.f / l_s[row];
        #pragma unroll
        for (int j = 0; j < 4; j++) {
            out[((size_t)b*SS + q0 + row)*EE + h*DD + tx*4 + j] = O[i][j]*inv;
        }
    }
}

// ---------------- router aux loss ----------------
__global__ void loss_kernel(const float* __restrict__ rlog, const int* __restrict__ dep,
                            float* __restrict__ loss) {
    int tid = threadIdx.x;  // 1024
    __shared__ float red[1024];
    float p[MAXD] = {0,0,0,0};
    float ds = 0.f;
    for (int n = tid; n < NN; n += 1024) {
        float l0 = rlog[n*4+0], l1 = rlog[n*4+1], l2 = rlog[n*4+2], l3 = rlog[n*4+3];
        float m = fmaxf(fmaxf(l0,l1), fmaxf(l2,l3));
        float e0 = expf(l0-m), e1 = expf(l1-m), e2 = expf(l2-m), e3 = expf(l3-m);
        float inv = 1.f/(e0+e1+e2+e3);
        p[0] += e0*inv; p[1] += e1*inv; p[2] += e2*inv; p[3] += e3*inv;
        ds += (float)dep[n];
    }
    float sums[5];
    float vals[5] = {p[0], p[1], p[2], p[3], ds};
    for (int v = 0; v < 5; v++) {
        red[tid] = vals[v]; __syncthreads();
        for (int o = 512; o > 0; o >>= 1) { if (tid < o) red[tid] += red[tid+o]; __syncthreads(); }
        sums[v] = red[0]; __syncthreads();
    }
    if (tid == 0) {
        const float u = 1.f/MAXD;
        float lb = 0.f;
        for (int m = 0; m < MAXD; m++) {
            float mp = sums[m] / (float)NN;
            lb += u * (logf(u) - logf(mp));
        }
        lb /= MAXD;
        float sparsity = (sums[4] / (float)NN) / MAXD;
        loss[0] = 0.01f*lb + 0.001f*sparsity;
    }
}

// ---------------- output tail ----------------
__global__ void finalize_kernel(const int* __restrict__ dep, const float* __restrict__ rlog,
                                const float* __restrict__ loss, float* __restrict__ out) {
    int i = blockIdx.x * blockDim.x + threadIdx.x;
    size_t base = (size_t)NN * VV;
    if (i < NN) out[base + i] = (float)dep[i];
    if (i == 0) out[base + NN] = loss[0];
    if (i < NN*MAXD) out[base + NN + 1 + i] = rlog[i];
}

// ---------------- host orchestration ----------------
extern "C" void kernel_launch(void* const* d_in, const int* in_sizes, int n_in,
                              void* d_out, int out_size) {
    const int*   ids  = (const int*)  d_in[0];
    const float* tok  = (const float*)d_in[1];
    const float* pos  = (const float*)d_in[2];
    const float* rw1  = (const float*)d_in[3];
    const float* rb1  = (const float*)d_in[4];
    const float* rw2  = (const float*)d_in[5];
    const float* rb2  = (const float*)d_in[6];
    const float* wqkv = (const float*)d_in[7];
    const float* bqkv = (const float*)d_in[8];
    const float* wo   = (const float*)d_in[9];
    const float* bo   = (const float*)d_in[10];
    const float* ln1g = (const float*)d_in[11];
    const float* ln1b = (const float*)d_in[12];
    const float* ln2g = (const float*)d_in[13];
    const float* ln2b = (const float*)d_in[14];
    const float* w1   = (const float*)d_in[15];
    const float* b1   = (const float*)d_in[16];
    const float* w2   = (const float*)d_in[17];
    const float* b2   = (const float*)d_in[18];
    const float* lnfg = (const float*)d_in[19];
    const float* lnfb = (const float*)d_in[20];
    const float* lmh  = (const float*)d_in[21];
    float* out = (float*)d_out;

    float *ph, *phn, *pqkv, *pattn, *pffa, *prl, *ploss;
    int* pdep;
    cudaGetSymbolAddress((void**)&ph,    g_h);
    cudaGetSymbolAddress((void**)&phn,   g_hn);
    cudaGetSymbolAddress((void**)&pqkv,  g_qkv);
    cudaGetSymbolAddress((void**)&pattn, g_attn);
    cudaGetSymbolAddress((void**)&pffa,  g_ffa);
    cudaGetSymbolAddress((void**)&prl,   g_rlog);
    cudaGetSymbolAddress((void**)&ploss, g_loss);
    cudaGetSymbolAddress((void**)&pdep,  g_dep);

    static const int ATTN_SMEM = (4*64*65 + 3*64) * sizeof(float) + 2*64*sizeof(int);
    cudaFuncSetAttribute(attn_tile_kernel, cudaFuncAttributeMaxDynamicSharedMemorySize, ATTN_SMEM);
    cudaFuncSetAttribute(gemm3x<0>, cudaFuncAttributeMaxDynamicSharedMemorySize, GEMM_SMEM);
    cudaFuncSetAttribute(gemm3x<1>, cudaFuncAttributeMaxDynamicSharedMemorySize, GEMM_SMEM);
    cudaFuncSetAttribute(gemm_lmh,  cudaFuncAttributeMaxDynamicSharedMemorySize, GEMM_SMEM);

    embed_kernel<<<(NN*EE + 255)/256, 256>>>(ids, tok, pos, ph);
    router_kernel<<<NN, RH>>>(ph, rw1, rb1, rw2, rb2, prl, pdep);

    for (int depth = 1; depth <= MAXD; depth++) {
        int li = depth - 1;
        ln_kernel<<<NN, 256>>>(ph, ln1g + li*EE, ln1b + li*EE, phn);
        {
            dim3 g(QKVW/128, NN/128);
            gemm3x<0><<<g, 256, GEMM_SMEM>>>(phn, wqkv + (size_t)li*QKVW*EE, bqkv + li*QKVW, pqkv, QKVW, EE);
        }
        attn_tile_kernel<<<dim3(SS/64, HH, BB), 256, ATTN_SMEM>>>(pqkv, pdep, depth, pattn);
        {
            // wo: split-K x2 into partial buffers (g_qkv reused; free here), then reduce
            dim3 g(EE/128, NN/128, 2);
            gemm3x<0><<<g, 256, GEMM_SMEM>>>(pattn, wo + (size_t)li*EE*EE, bo + li*EE, pqkv, EE, EE);
            add2_kernel<<<(NN*EE + 255)/256, 256>>>(ph, pqkv, pqkv + (size_t)NN*EE);
        }
        ln_kernel<<<NN, 256>>>(ph, ln2g + li*EE, ln2b + li*EE, phn);
        {
            dim3 g(II/128, NN/128);
            gemm3x<1><<<g, 256, GEMM_SMEM>>>(phn, w1 + (size_t)li*II*EE, b1 + li*II, pffa, II, EE);
        }
        {
            // w2: split-K x2 (K=3072 -> 1536 per part, 192 CTAs), then reduce
            dim3 g(EE/128, NN/128, 2);
            gemm3x<0><<<g, 256, GEMM_SMEM>>>(pffa, w2 + (size_t)li*EE*II, b2 + li*EE, pqkv, EE, II);
            add2_kernel<<<(NN*EE + 255)/256, 256>>>(ph, pqkv, pqkv + (size_t)NN*EE);
        }
    }

    ln_kernel<<<NN, 256>>>(ph, lnfg, lnfb, phn);
    {
        dim3 g(NN/128, (VV + 127)/128);   // x = m-tile, y = n-tile (W reuse in L2)
        gemm_lmh<<<g, 256, GEMM_SMEM>>>(phn, lmh, out, VV, EE);
    }

    loss_kernel<<<1, 1024>>>(prl, pdep, ploss);

    long long full = (long long)NN*VV + NN + 1 + (long long)NN*MAXD;
    if ((long long)out_size >= full)
        finalize_kernel<<<(NN*MAXD + 255)/256, 256>>>(pdep, prl, ploss, out);
}